// round 3
// baseline (speedup 1.0000x reference)
#include <cuda_runtime.h>

// ---------------- problem constants ----------------
#define BATCH 1024
#define C0_ 512
#define C1_ 1024
#define K0_ 100
#define K1_ 50
#define ROWS0 (BATCH*C0_)   // 524288
#define ROWS1 (BATCH*C1_)   // 1048576

// ---------------- scratch (no allocation allowed) ----------------
__device__ float g_pooled0[ROWS0];
__device__ float g_pooled1[ROWS1];
__device__ float g_accum[4];   // [num0, den0, num1, den1]

// ---------------- pool feat0: warp per (b,c) row, 49 float4 per row --------
__global__ void pool0_kernel(const float* __restrict__ feat0) {
    if (blockIdx.x == 0 && threadIdx.x < 4) g_accum[threadIdx.x] = 0.0f;
    const unsigned wid  = (blockIdx.x * blockDim.x + threadIdx.x) >> 5;
    const unsigned lane = threadIdx.x & 31u;
    if (wid >= ROWS0) return;
    const float4* src = reinterpret_cast<const float4*>(feat0) + (size_t)wid * 49;
    float4 a = __ldcs(src + lane);
    float  s = a.x + a.y + a.z + a.w;
    if (lane < 17u) {
        float4 c = __ldcs(src + 32u + lane);
        s += c.x + c.y + c.z + c.w;
    }
    #pragma unroll
    for (int o = 16; o; o >>= 1) s += __shfl_xor_sync(0xffffffffu, s, o);
    if (lane == 0u) g_pooled0[wid] = s * (1.0f / 196.0f);
}

// ---------------- pool feat1: block tiles 256 rows via smem ----------------
#define P1_RPB 256
#define P1_FLT (P1_RPB*49)      // 12544
#define P1_VEC (P1_FLT/4)       // 3136
__global__ void pool1_kernel(const float* __restrict__ feat1) {
    __shared__ float sf[P1_FLT];
    const size_t base = (size_t)blockIdx.x * P1_FLT;
    const float4* src = reinterpret_cast<const float4*>(feat1 + base);
    float4* dst = reinterpret_cast<float4*>(sf);
    for (int i = threadIdx.x; i < P1_VEC; i += blockDim.x)
        dst[i] = __ldcs(src + i);
    __syncthreads();
    const int t = threadIdx.x;
    const float* r = sf + t * 49;
    float s0 = 0.f, s1 = 0.f, s2 = 0.f, s3 = 0.f;
    #pragma unroll
    for (int e = 0; e < 48; e += 4) {
        s0 += r[e]; s1 += r[e+1]; s2 += r[e+2]; s3 += r[e+3];
    }
    const float s = s0 + s1 + s2 + s3 + r[48];
    g_pooled1[(size_t)blockIdx.x * P1_RPB + t] = s * (1.0f / 49.0f);
}

// ---------------- head kernel: one warp per batch row, one head per launch -
// W for a single head is 200KB -> fits L1 (228KB). All 8 warps of a block
// (and all blocks of this launch resident on an SM) reuse the same W from L1.
// float4 loads; 2 k's per iteration for ILP.
template<int C, int K, int AOFF>
__global__ void __launch_bounds__(256)
head_kernel(const float* __restrict__ pooled,
            const float* __restrict__ W, const float* __restrict__ bias,
            const int* __restrict__ lut, const float* __restrict__ cw,
            const int* __restrict__ target)
{
    __shared__ float slg[8][K + 8];
    const int w    = threadIdx.x >> 5;
    const int lane = threadIdx.x & 31;
    const int b    = blockIdx.x * 8 + w;

    constexpr int NV = C / 128;   // float4 per lane (4 or 8)
    float4 p[NV];
    const float4* pr = reinterpret_cast<const float4*>(pooled + (size_t)b * C) + lane;
    #pragma unroll
    for (int i = 0; i < NV; i++) p[i] = pr[i * 32];

    #pragma unroll 1
    for (int k = 0; k < K; k += 2) {
        const float4* w0 = reinterpret_cast<const float4*>(W + (size_t)k * C) + lane;
        const float4* w1 = reinterpret_cast<const float4*>(W + (size_t)(k + 1) * C) + lane;
        float a0 = 0.f, a1 = 0.f;
        #pragma unroll
        for (int i = 0; i < NV; i++) {
            float4 x = w0[i * 32];
            float4 y = w1[i * 32];
            a0 = fmaf(p[i].x, x.x, a0); a0 = fmaf(p[i].y, x.y, a0);
            a0 = fmaf(p[i].z, x.z, a0); a0 = fmaf(p[i].w, x.w, a0);
            a1 = fmaf(p[i].x, y.x, a1); a1 = fmaf(p[i].y, y.y, a1);
            a1 = fmaf(p[i].z, y.z, a1); a1 = fmaf(p[i].w, y.w, a1);
        }
        #pragma unroll
        for (int o = 16; o; o >>= 1) {
            a0 += __shfl_xor_sync(0xffffffffu, a0, o);
            a1 += __shfl_xor_sync(0xffffffffu, a1, o);
        }
        if (lane == 0) {
            slg[w][k]     = a0 + bias[k];
            slg[w][k + 1] = a1 + bias[k + 1];
        }
    }
    __syncwarp();

    // softmax + weighted NLL for this row
    float m = -3.4e38f;
    for (int k = lane; k < K; k += 32) m = fmaxf(m, slg[w][k]);
    #pragma unroll
    for (int o = 16; o; o >>= 1) m = fmaxf(m, __shfl_xor_sync(0xffffffffu, m, o));
    float s = 0.0f;
    for (int k = lane; k < K; k += 32) s += __expf(slg[w][k] - m);
    #pragma unroll
    for (int o = 16; o; o >>= 1) s += __shfl_xor_sync(0xffffffffu, s, o);

    if (lane == 0) {
        const int   t   = lut[target[b]];
        const float nll = m + __logf(s) - slg[w][t];
        const float wt  = cw[t];
        atomicAdd(&g_accum[AOFF],     wt * nll);
        atomicAdd(&g_accum[AOFF + 1], wt);
    }
}

// ---------------- finalize ----------------
__global__ void finalize_kernel(float* __restrict__ out) {
    out[0] = g_accum[0] / g_accum[1] + g_accum[2] / g_accum[3];
}

// ---------------- launch ----------------
extern "C" void kernel_launch(void* const* d_in, const int* in_sizes, int n_in,
                              void* d_out, int out_size) {
    (void)in_sizes; (void)n_in; (void)out_size;
    const float* feat0  = (const float*)d_in[0];
    const float* feat1  = (const float*)d_in[1];
    const float* W0     = (const float*)d_in[2];
    const float* b0v    = (const float*)d_in[3];
    const float* W1     = (const float*)d_in[4];
    const float* b1v    = (const float*)d_in[5];
    const int*   lut0   = (const int*)d_in[6];
    const int*   lut1   = (const int*)d_in[7];
    const float* cw0    = (const float*)d_in[8];
    const float* cw1    = (const float*)d_in[9];
    const int*   target = (const int*)d_in[10];
    float* out = (float*)d_out;

    // feat0: warp per row (also zeros g_accum in block 0)
    pool0_kernel<<<(ROWS0 * 32) / 256, 256>>>(feat0);
    // feat1: 256 rows per block
    pool1_kernel<<<ROWS1 / P1_RPB, P1_RPB>>>(feat1);

    // one head per launch: W stays L1-resident per SM
    head_kernel<C0_, K0_, 0><<<BATCH / 8, 256>>>(g_pooled0, W0, b0v, lut0, cw0, target);
    head_kernel<C1_, K1_, 2><<<BATCH / 8, 256>>>(g_pooled1, W1, b1v, lut1, cw1, target);

    finalize_kernel<<<1, 1>>>(out);
}

// round 4
// speedup vs baseline: 1.4013x; 1.4013x over previous
#include <cuda_runtime.h>

// ---------------- problem constants ----------------
#define BATCH 1024
#define C0_ 512
#define C1_ 1024
#define K0_ 100
#define K1_ 50
#define KP0 128           // K0 padded to 32*TK0
#define KP1 64            // K1 padded
#define ROWS0 (BATCH*C0_)   // 524288
#define ROWS1 (BATCH*C1_)   // 1048576

#define MB 16             // batch rows per block
#define CC 64             // C-chunk
#define PITCH0 132        // KP0+4 : 16B-aligned rows, conflict-free reads
#define PITCH1 68         // KP1+4

// ---------------- scratch (no allocation allowed) ----------------
__device__ float g_pooled0[ROWS0];
__device__ float g_pooled1[ROWS1];
__device__ float g_accum[4];   // [num0, den0, num1, den1]

// ---------------- pool feat0: warp per (b,c) row, 49 float4 per row --------
__global__ void pool0_kernel(const float* __restrict__ feat0) {
    if (blockIdx.x == 0 && threadIdx.x < 4) g_accum[threadIdx.x] = 0.0f;
    const unsigned wid  = (blockIdx.x * blockDim.x + threadIdx.x) >> 5;
    const unsigned lane = threadIdx.x & 31u;
    if (wid >= ROWS0) return;
    const float4* src = reinterpret_cast<const float4*>(feat0) + (size_t)wid * 49;
    float4 a = __ldcs(src + lane);
    float  s = a.x + a.y + a.z + a.w;
    if (lane < 17u) {
        float4 c = __ldcs(src + 32u + lane);
        s += c.x + c.y + c.z + c.w;
    }
    #pragma unroll
    for (int o = 16; o; o >>= 1) s += __shfl_xor_sync(0xffffffffu, s, o);
    if (lane == 0u) g_pooled0[wid] = s * (1.0f / 196.0f);
}

// ---------------- pool feat1: block tiles 256 rows via smem ----------------
#define P1_RPB 256
#define P1_FLT (P1_RPB*49)      // 12544
#define P1_VEC (P1_FLT/4)       // 3136
__global__ void pool1_kernel(const float* __restrict__ feat1) {
    __shared__ float sf[P1_FLT];
    const size_t base = (size_t)blockIdx.x * P1_FLT;
    const float4* src = reinterpret_cast<const float4*>(feat1 + base);
    float4* dst = reinterpret_cast<float4*>(sf);
    for (int i = threadIdx.x; i < P1_VEC; i += blockDim.x)
        dst[i] = __ldcs(src + i);
    __syncthreads();
    const int t = threadIdx.x;
    const float* r = sf + t * 49;
    float s0 = 0.f, s1 = 0.f, s2 = 0.f, s3 = 0.f;
    #pragma unroll
    for (int e = 0; e < 48; e += 4) {
        s0 += r[e]; s1 += r[e+1]; s2 += r[e+2]; s3 += r[e+3];
    }
    const float s = s0 + s1 + s2 + s3 + r[48];
    g_pooled1[(size_t)blockIdx.x * P1_RPB + t] = s * (1.0f / 49.0f);
}

// ---------------- fused head tile: smem-tiled GEMM + softmax-CE ------------
// Block owns MB=16 batch rows of one head. Loops over all C chunks of CC=64:
// stages pooled tile [16][64] + W chunk transposed [64][KPAD] in smem;
// 256 threads = 4 b-groups x 64 k-groups, each thread a 4b x TK register tile.
// Then full softmax-CE for the 16 rows from smem logits; atomic num/den.
#define SMEM_BYTES (4*(MB*CC + CC*PITCH0 + MB*PITCH0))   // 46336

template<int C, int K, int KPAD, int TK, int PITCH, int AOFF>
__device__ __forceinline__ void head_tile(
    const float* __restrict__ pooled,
    const float* __restrict__ W, const float* __restrict__ bias,
    const int* __restrict__ lut, const float* __restrict__ cw,
    const int* __restrict__ target, int m0, char* sraw)
{
    float (*sp)[CC]     = reinterpret_cast<float(*)[CC]>(sraw);
    float (*swt)[PITCH] = reinterpret_cast<float(*)[PITCH]>(sraw + sizeof(float)*MB*CC);
    float (*slg)[PITCH] = reinterpret_cast<float(*)[PITCH]>(sraw + sizeof(float)*(MB*CC + CC*PITCH));

    const int tid = threadIdx.x;
    const int ktg = tid & 63;      // k-group 0..63
    const int bt  = tid >> 6;      // b-group 0..3 (4 rows each)

    float acc[4][TK];
    #pragma unroll
    for (int j = 0; j < 4; j++)
        #pragma unroll
        for (int t = 0; t < TK; t++) acc[j][t] = 0.0f;

    for (int c0 = 0; c0 < C; c0 += CC) {
        // stage pooled tile: 256 float4, one per thread, coalesced
        {
            const int row = tid >> 4;       // 0..15
            const int c4  = tid & 15;       // 0..15
            float4 v = *reinterpret_cast<const float4*>(
                pooled + (size_t)(m0 + row) * C + c0 + c4 * 4);
            *reinterpret_cast<float4*>(&sp[row][c4 * 4]) = v;
        }
        // stage W chunk transposed: gmem coalesced along c, zero-pad k>=K
        #pragma unroll
        for (int idx = tid; idx < KPAD * CC; idx += 256) {
            const int c = idx & (CC - 1);
            const int k = idx >> 6;
            swt[c][k] = (k < K) ? W[(size_t)k * C + c0 + c] : 0.0f;
        }
        __syncthreads();

        // compute: register tile 4b x TK over CC c's
        #pragma unroll 4
        for (int c4 = 0; c4 < CC / 4; c4++) {
            float pv[4][4];
            #pragma unroll
            for (int j = 0; j < 4; j++) {
                float4 v = *reinterpret_cast<const float4*>(&sp[bt * 4 + j][c4 * 4]);
                pv[j][0] = v.x; pv[j][1] = v.y; pv[j][2] = v.z; pv[j][3] = v.w;
            }
            #pragma unroll
            for (int cc = 0; cc < 4; cc++) {
                const int c = c4 * 4 + cc;
                if (TK == 2) {
                    float2 wv = *reinterpret_cast<const float2*>(&swt[c][ktg * 2]);
                    #pragma unroll
                    for (int j = 0; j < 4; j++) {
                        acc[j][0] = fmaf(pv[j][cc], wv.x, acc[j][0]);
                        acc[j][1] = fmaf(pv[j][cc], wv.y, acc[j][1]);
                    }
                } else {
                    float wv = swt[c][ktg];
                    #pragma unroll
                    for (int j = 0; j < 4; j++)
                        acc[j][0] = fmaf(pv[j][cc], wv, acc[j][0]);
                }
            }
        }
        __syncthreads();
    }

    // logits -> smem (with bias)
    #pragma unroll
    for (int t = 0; t < TK; t++) {
        const int k = ktg * TK + t;
        const float bv = (k < K) ? bias[k] : 0.0f;
        #pragma unroll
        for (int j = 0; j < 4; j++)
            slg[bt * 4 + j][k] = acc[j][t] + bv;
    }
    __syncthreads();

    // softmax-CE: warp w handles rows w, w+8
    const int w = tid >> 5, lane = tid & 31;
    #pragma unroll
    for (int r = w; r < MB; r += 8) {
        float m = -3.4e38f;
        for (int k = lane; k < K; k += 32) m = fmaxf(m, slg[r][k]);
        #pragma unroll
        for (int o = 16; o; o >>= 1) m = fmaxf(m, __shfl_xor_sync(0xffffffffu, m, o));
        float s = 0.0f;
        for (int k = lane; k < K; k += 32) s += __expf(slg[r][k] - m);
        #pragma unroll
        for (int o = 16; o; o >>= 1) s += __shfl_xor_sync(0xffffffffu, s, o);
        if (lane == 0) {
            const int b = m0 + r;
            const int t = lut[target[b]];
            const float nll = m + __logf(s) - slg[r][t];
            const float wt  = cw[t];
            atomicAdd(&g_accum[AOFF],     wt * nll);
            atomicAdd(&g_accum[AOFF + 1], wt);
        }
    }
}

__global__ void __launch_bounds__(256)
heads_kernel(const float* __restrict__ W0, const float* __restrict__ b0v,
             const int* __restrict__ lut0, const float* __restrict__ cw0,
             const float* __restrict__ W1, const float* __restrict__ b1v,
             const int* __restrict__ lut1, const float* __restrict__ cw1,
             const int* __restrict__ target)
{
    __shared__ __align__(16) char sraw[SMEM_BYTES];
    if (blockIdx.x < BATCH / MB)
        head_tile<C0_, K0_, KP0, 2, PITCH0, 0>(
            g_pooled0, W0, b0v, lut0, cw0, target, blockIdx.x * MB, sraw);
    else
        head_tile<C1_, K1_, KP1, 1, PITCH1, 2>(
            g_pooled1, W1, b1v, lut1, cw1, target,
            (blockIdx.x - BATCH / MB) * MB, sraw);
}

// ---------------- finalize ----------------
__global__ void finalize_kernel(float* __restrict__ out) {
    out[0] = g_accum[0] / g_accum[1] + g_accum[2] / g_accum[3];
}

// ---------------- launch ----------------
extern "C" void kernel_launch(void* const* d_in, const int* in_sizes, int n_in,
                              void* d_out, int out_size) {
    (void)in_sizes; (void)n_in; (void)out_size;
    const float* feat0  = (const float*)d_in[0];
    const float* feat1  = (const float*)d_in[1];
    const float* W0     = (const float*)d_in[2];
    const float* b0v    = (const float*)d_in[3];
    const float* W1     = (const float*)d_in[4];
    const float* b1v    = (const float*)d_in[5];
    const int*   lut0   = (const int*)d_in[6];
    const int*   lut1   = (const int*)d_in[7];
    const float* cw0    = (const float*)d_in[8];
    const float* cw1    = (const float*)d_in[9];
    const int*   target = (const int*)d_in[10];
    float* out = (float*)d_out;

    // feat0: warp per row (also zeros g_accum in block 0)
    pool0_kernel<<<(ROWS0 * 32) / 256, 256>>>(feat0);
    // feat1: 256 rows per block
    pool1_kernel<<<ROWS1 / P1_RPB, P1_RPB>>>(feat1);

    // fused heads: 64 blocks head0 + 64 blocks head1, one wave
    heads_kernel<<<2 * (BATCH / MB), 256>>>(W0, b0v, lut0, cw0,
                                            W1, b1v, lut1, cw1, target);

    finalize_kernel<<<1, 1>>>(out);
}